// round 1
// baseline (speedup 1.0000x reference)
#include <cuda_runtime.h>

#define SS 7
#define NCLS 80
#define PRED_D 90   // B*5 + C = 2*5 + 80
#define TGT_D 85    // 5 + C

// Accumulators: [0]=xy [1]=wh [2]=conf_obj [3]=conf_noobj [4]=class
__device__ double g_acc[8];

__global__ void zero_acc_kernel() {
    if (threadIdx.x < 8) g_acc[threadIdx.x] = 0.0;
}

// IoU of target box (corners) vs one predicted box (rel x,y,w,h in cell fi,fj)
__device__ __forceinline__ float iou_vs(
    float tx1, float ty1, float tx2, float ty2,
    float px, float py, float pw, float ph,
    float fi, float fj)
{
    const float invS = 1.0f / 7.0f;
    float xc = (px + fj) * invS;
    float yc = (py + fi) * invS;
    float x1 = xc - pw * 0.5f, x2 = xc + pw * 0.5f;
    float y1 = yc - ph * 0.5f, y2 = yc + ph * 0.5f;
    float iw = fminf(tx2, x2) - fmaxf(tx1, x1);
    float ih = fminf(ty2, y2) - fmaxf(ty1, y1);
    iw = fmaxf(iw, 0.0f);
    ih = fmaxf(ih, 0.0f);
    float inter = iw * ih;
    float area_a = (tx2 - tx1) * (ty2 - ty1);
    float area_b = (x2 - x1) * (y2 - y1);
    return inter / (area_a + area_b - inter + 1e-6f);
}

__global__ void __launch_bounds__(256, 8)
yolo_loss_kernel(const float* __restrict__ pred,
                 const float* __restrict__ tgt,
                 int ncells)
{
    const int lane  = threadIdx.x & 31;
    const int gwarp = (blockIdx.x * blockDim.x + threadIdx.x) >> 5;
    const int nwarp = (gridDim.x * blockDim.x) >> 5;

    float a_xy = 0.0f, a_wh = 0.0f, a_co = 0.0f, a_cn = 0.0f, a_cls = 0.0f;

    for (int cell = gwarp; cell < ncells; cell += nwarp) {
        const long long bp = (long long)cell * PRED_D;
        const long long bt = (long long)cell * TGT_D;

        // Warp-uniform load of target confidence (single 32B sector)
        float tc = __ldg(&tgt[bt + 4]);

        if (tc == 0.0f) {
            // No-object cell: only the noobj confidence term survives.
            if (lane == 0) {
                float pc = __ldg(&pred[bp + 9]);
                a_cn += pc * pc;   // (0 - pc)^2
            }
            continue;
        }

        // ----- object cell: full loss -----
        const int ij = cell % 49;
        const float fi = (float)(ij / 7);
        const float fj = (float)(ij % 7);

        // Warp-uniform scalar loads of the two pred boxes + target box
        float p0 = __ldg(&pred[bp + 0]);
        float p1 = __ldg(&pred[bp + 1]);
        float p2 = __ldg(&pred[bp + 2]);
        float p3 = __ldg(&pred[bp + 3]);
        float p5 = __ldg(&pred[bp + 5]);
        float p6 = __ldg(&pred[bp + 6]);
        float p7 = __ldg(&pred[bp + 7]);
        float p8 = __ldg(&pred[bp + 8]);
        float p9 = __ldg(&pred[bp + 9]);
        float t0 = __ldg(&tgt[bt + 0]);
        float t1 = __ldg(&tgt[bt + 1]);
        float t2 = __ldg(&tgt[bt + 2]);
        float t3 = __ldg(&tgt[bt + 3]);

        if (lane == 0) {
            const float invS = 1.0f / 7.0f;
            float txc = (t0 + fj) * invS;
            float tyc = (t1 + fi) * invS;
            float tx1 = txc - t2 * 0.5f, tx2c = txc + t2 * 0.5f;
            float ty1 = tyc - t3 * 0.5f, ty2c = tyc + t3 * 0.5f;

            float iou0 = iou_vs(tx1, ty1, tx2c, ty2c, p0, p1, p2, p3, fi, fj);
            float iou1 = iou_vs(tx1, ty1, tx2c, ty2c, p5, p6, p7, p8, fi, fj);

            bool sel = (iou0 > iou1);   // true -> box1
            float sx = sel ? p5 : p0;
            float sy = sel ? p6 : p1;
            float sw = sel ? p7 : p2;
            float sh = sel ? p8 : p3;

            float dx = t0 - sx, dy = t1 - sy;
            a_xy += dx * dx + dy * dy;

            float dw = sqrtf(t2) - sqrtf(fmaxf(sw, 0.0f));
            float dh = sqrtf(t3) - sqrtf(fmaxf(sh, 0.0f));
            a_wh += dw * dw + dh * dh;

            float dc = tc - p9;
            a_co += dc * dc;
        }

        // Class loss: 80 pairs, coalesced across the warp
        #pragma unroll
        for (int base = 0; base < NCLS; base += 32) {
            int c = base + lane;
            if (c < NCLS) {
                float tcl = __ldg(&tgt[bt + 5 + c]);
                float pcl = __ldg(&pred[bp + 10 + c]);
                float d = tcl - pcl;
                a_cls += d * d;
            }
        }
    }

    // Warp reduction
    #pragma unroll
    for (int off = 16; off > 0; off >>= 1) {
        a_xy  += __shfl_xor_sync(0xffffffffu, a_xy,  off);
        a_wh  += __shfl_xor_sync(0xffffffffu, a_wh,  off);
        a_co  += __shfl_xor_sync(0xffffffffu, a_co,  off);
        a_cn  += __shfl_xor_sync(0xffffffffu, a_cn,  off);
        a_cls += __shfl_xor_sync(0xffffffffu, a_cls, off);
    }

    // Block reduction (8 warps)
    __shared__ float s_red[5][8];
    const int wib = threadIdx.x >> 5;
    if (lane == 0) {
        s_red[0][wib] = a_xy;
        s_red[1][wib] = a_wh;
        s_red[2][wib] = a_co;
        s_red[3][wib] = a_cn;
        s_red[4][wib] = a_cls;
    }
    __syncthreads();
    if (threadIdx.x < 5) {
        double sum = 0.0;
        #pragma unroll
        for (int w = 0; w < 8; w++) sum += (double)s_red[threadIdx.x][w];
        atomicAdd(&g_acc[threadIdx.x], sum);
    }
}

__global__ void finalize_kernel(float* __restrict__ out, double inv_bs) {
    if (threadIdx.x == 0 && blockIdx.x == 0) {
        double lxy  = g_acc[0] * inv_bs;
        double lwh  = g_acc[1] * inv_bs;
        double lco  = g_acc[2] * inv_bs;
        double lcn  = g_acc[3] * inv_bs;
        double lcls = g_acc[4] * inv_bs;
        double loss = (5.0 * lxy + 5.0 * lwh + lco + 0.5 * lcn + lcls) * inv_bs;
        out[0] = (float)loss;
        out[1] = (float)lxy;
        out[2] = (float)lwh;
        out[3] = (float)lco;
        out[4] = (float)lcn;
        out[5] = (float)lcls;
    }
}

extern "C" void kernel_launch(void* const* d_in, const int* in_sizes, int n_in,
                              void* d_out, int out_size)
{
    const float* pred = (const float*)d_in[0];
    const float* tgt  = (const float*)d_in[1];
    float* out = (float*)d_out;

    const int N = in_sizes[0] / (49 * PRED_D);   // batch size
    const int ncells = N * 49;

    zero_acc_kernel<<<1, 32>>>();

    const int threads = 256;
    const int blocks  = 1184;   // 148 SMs * 8 blocks, grid-stride over cells
    yolo_loss_kernel<<<blocks, threads>>>(pred, tgt, ncells);

    finalize_kernel<<<1, 32>>>(out, 1.0 / (double)N);
}

// round 2
// speedup vs baseline: 1.1203x; 1.1203x over previous
#include <cuda_runtime.h>

#define NCLS 80
#define PRED_D 90   // B*5 + C
#define TGT_D 85    // 5 + C
#define TILE 512
#define THREADS 256
#define NWARPS (THREADS / 32)

// Accumulators: [0]=xy [1]=wh [2]=conf_obj [3]=conf_noobj [4]=class
__device__ double g_acc[8];

__global__ void zero_acc_kernel() {
    if (threadIdx.x < 8) g_acc[threadIdx.x] = 0.0;
}

__device__ __forceinline__ float iou_vs(
    float tx1, float ty1, float tx2, float ty2,
    float px, float py, float pw, float ph,
    float fi, float fj)
{
    const float invS = 1.0f / 7.0f;
    float xc = (px + fj) * invS;
    float yc = (py + fi) * invS;
    float x1 = xc - pw * 0.5f, x2 = xc + pw * 0.5f;
    float y1 = yc - ph * 0.5f, y2 = yc + ph * 0.5f;
    float iw = fmaxf(fminf(tx2, x2) - fmaxf(tx1, x1), 0.0f);
    float ih = fmaxf(fminf(ty2, y2) - fmaxf(ty1, y1), 0.0f);
    float inter = iw * ih;
    float area_a = (tx2 - tx1) * (ty2 - ty1);
    float area_b = (x2 - x1) * (y2 - y1);
    return inter / (area_a + area_b - inter + 1e-6f);
}

__global__ void __launch_bounds__(THREADS)
yolo_loss_kernel(const float* __restrict__ pred,
                 const float* __restrict__ tgt,
                 int ncells)
{
    __shared__ int   s_list[TILE];
    __shared__ int   s_cnt;
    __shared__ float s_red[5][NWARPS];

    const int tid  = threadIdx.x;
    const int lane = tid & 31;
    const int wid  = tid >> 5;

    if (tid == 0) s_cnt = 0;
    __syncthreads();

    const int base = blockIdx.x * TILE;

    float a_cn = 0.0f;

    // ---------------- Phase 1: scan, noobj loss, compact object cells ----
    // Batch all loads first (independent), then consume.
    float tc_v[TILE / THREADS];
    float pc_v[TILE / THREADS];
    int   cell_v[TILE / THREADS];

    #pragma unroll
    for (int k = 0; k < TILE / THREADS; k++) {
        int cell = base + k * THREADS + tid;
        cell_v[k] = cell;
        tc_v[k] = 0.0f;
        pc_v[k] = 0.0f;
        if (cell < ncells) {
            tc_v[k] = __ldg(&tgt[(long long)cell * TGT_D + 4]);
            pc_v[k] = __ldg(&pred[(long long)cell * PRED_D + 9]);
        }
    }

    #pragma unroll
    for (int k = 0; k < TILE / THREADS; k++) {
        int cell = cell_v[k];
        if (cell < ncells) {
            if (tc_v[k] == 0.0f) {
                a_cn += pc_v[k] * pc_v[k];
            } else {
                int pos = atomicAdd(&s_cnt, 1);
                s_list[pos] = cell;
            }
        }
    }
    __syncthreads();

    const int nobj = s_cnt;

    // ---------------- Phase 2: object cells, warp-cooperative ------------
    float a_xy = 0.0f, a_wh = 0.0f, a_co = 0.0f, a_cls = 0.0f;

    for (int k = wid; k < nobj; k += NWARPS) {
        const int cell = s_list[k];
        const long long bp = (long long)cell * PRED_D;
        const long long bt = (long long)cell * TGT_D;

        // Box scalars: 2 predicated loads across lanes
        float pb = (lane < 10) ? __ldg(&pred[bp + lane]) : 0.0f;
        float tb = (lane < 5)  ? __ldg(&tgt[bt + lane])  : 0.0f;

        // Class vectors: 80 = 32 + 32 + 16, coalesced, all independent
        float pc0 = __ldg(&pred[bp + 10 + lane]);
        float pc1 = __ldg(&pred[bp + 42 + lane]);
        float pc2 = (lane < 16) ? __ldg(&pred[bp + 74 + lane]) : 0.0f;
        float tg0 = __ldg(&tgt[bt + 5 + lane]);
        float tg1 = __ldg(&tgt[bt + 37 + lane]);
        float tg2 = (lane < 16) ? __ldg(&tgt[bt + 69 + lane]) : 0.0f;

        float d0 = tg0 - pc0, d1 = tg1 - pc1, d2 = tg2 - pc2;
        a_cls += d0 * d0 + d1 * d1 + d2 * d2;

        // Broadcast box scalars to all lanes
        float p0 = __shfl_sync(0xffffffffu, pb, 0);
        float p1 = __shfl_sync(0xffffffffu, pb, 1);
        float p2 = __shfl_sync(0xffffffffu, pb, 2);
        float p3 = __shfl_sync(0xffffffffu, pb, 3);
        float p5 = __shfl_sync(0xffffffffu, pb, 5);
        float p6 = __shfl_sync(0xffffffffu, pb, 6);
        float p7 = __shfl_sync(0xffffffffu, pb, 7);
        float p8 = __shfl_sync(0xffffffffu, pb, 8);
        float p9 = __shfl_sync(0xffffffffu, pb, 9);
        float t0 = __shfl_sync(0xffffffffu, tb, 0);
        float t1 = __shfl_sync(0xffffffffu, tb, 1);
        float t2 = __shfl_sync(0xffffffffu, tb, 2);
        float t3 = __shfl_sync(0xffffffffu, tb, 3);
        float t4 = __shfl_sync(0xffffffffu, tb, 4);

        const int ij = cell % 49;
        const float fi = (float)(ij / 7);
        const float fj = (float)(ij % 7);

        const float invS = 1.0f / 7.0f;
        float txc = (t0 + fj) * invS;
        float tyc = (t1 + fi) * invS;
        float tx1 = txc - t2 * 0.5f, tx2c = txc + t2 * 0.5f;
        float ty1 = tyc - t3 * 0.5f, ty2c = tyc + t3 * 0.5f;

        float iou0 = iou_vs(tx1, ty1, tx2c, ty2c, p0, p1, p2, p3, fi, fj);
        float iou1 = iou_vs(tx1, ty1, tx2c, ty2c, p5, p6, p7, p8, fi, fj);

        bool sel = (iou0 > iou1);   // true -> second box
        float sx = sel ? p5 : p0;
        float sy = sel ? p6 : p1;
        float sw = sel ? p7 : p2;
        float sh = sel ? p8 : p3;

        if (lane == 0) {
            float dx = t0 - sx, dy = t1 - sy;
            a_xy += dx * dx + dy * dy;

            float dw = sqrtf(t2) - sqrtf(fmaxf(sw, 0.0f));
            float dh = sqrtf(t3) - sqrtf(fmaxf(sh, 0.0f));
            a_wh += dw * dw + dh * dh;

            float dc = t4 - p9;
            a_co += dc * dc;
        }
    }

    // ---------------- Reduction ----------------
    #pragma unroll
    for (int off = 16; off > 0; off >>= 1) {
        a_xy  += __shfl_xor_sync(0xffffffffu, a_xy,  off);
        a_wh  += __shfl_xor_sync(0xffffffffu, a_wh,  off);
        a_co  += __shfl_xor_sync(0xffffffffu, a_co,  off);
        a_cn  += __shfl_xor_sync(0xffffffffu, a_cn,  off);
        a_cls += __shfl_xor_sync(0xffffffffu, a_cls, off);
    }

    if (lane == 0) {
        s_red[0][wid] = a_xy;
        s_red[1][wid] = a_wh;
        s_red[2][wid] = a_co;
        s_red[3][wid] = a_cn;
        s_red[4][wid] = a_cls;
    }
    __syncthreads();

    if (tid < 5) {
        double sum = 0.0;
        #pragma unroll
        for (int w = 0; w < NWARPS; w++) sum += (double)s_red[tid][w];
        atomicAdd(&g_acc[tid], sum);
    }
}

__global__ void finalize_kernel(float* __restrict__ out, double inv_bs) {
    if (threadIdx.x == 0 && blockIdx.x == 0) {
        double lxy  = g_acc[0] * inv_bs;
        double lwh  = g_acc[1] * inv_bs;
        double lco  = g_acc[2] * inv_bs;
        double lcn  = g_acc[3] * inv_bs;
        double lcls = g_acc[4] * inv_bs;
        double loss = (5.0 * lxy + 5.0 * lwh + lco + 0.5 * lcn + lcls) * inv_bs;
        out[0] = (float)loss;
        out[1] = (float)lxy;
        out[2] = (float)lwh;
        out[3] = (float)lco;
        out[4] = (float)lcn;
        out[5] = (float)lcls;
    }
}

extern "C" void kernel_launch(void* const* d_in, const int* in_sizes, int n_in,
                              void* d_out, int out_size)
{
    const float* pred = (const float*)d_in[0];
    const float* tgt  = (const float*)d_in[1];
    float* out = (float*)d_out;

    const int N = in_sizes[0] / (49 * PRED_D);
    const int ncells = N * 49;
    const int blocks = (ncells + TILE - 1) / TILE;

    zero_acc_kernel<<<1, 32>>>();
    yolo_loss_kernel<<<blocks, THREADS>>>(pred, tgt, ncells);
    finalize_kernel<<<1, 32>>>(out, 1.0 / (double)N);
}

// round 3
// speedup vs baseline: 1.1703x; 1.0447x over previous
#include <cuda_runtime.h>

#define NCLS 80
#define PRED_D 90   // B*5 + C
#define TGT_D 85    // 5 + C
#define TILE 512
#define THREADS 256
#define NWARPS (THREADS / 32)
#define PERT (TILE / THREADS)

// Accumulators: [0]=xy [1]=wh [2]=conf_obj [3]=conf_noobj [4]=class
__device__ double g_acc[5];
__device__ unsigned int g_done;

struct Ld {
    float pb, tb, pc0, pc1, pc2, tg0, tg1, tg2;
};

__device__ __forceinline__ Ld load_cell(const float* __restrict__ pred,
                                        const float* __restrict__ tgt,
                                        int cell, int lane)
{
    Ld r;
    const long long bp = (long long)cell * PRED_D;
    const long long bt = (long long)cell * TGT_D;
    r.pb  = (lane < 10) ? __ldg(&pred[bp + lane])      : 0.0f;
    r.tb  = (lane < 5)  ? __ldg(&tgt[bt + lane])       : 0.0f;
    r.pc0 = __ldg(&pred[bp + 10 + lane]);
    r.pc1 = __ldg(&pred[bp + 42 + lane]);
    r.pc2 = (lane < 16) ? __ldg(&pred[bp + 74 + lane]) : 0.0f;
    r.tg0 = __ldg(&tgt[bt + 5 + lane]);
    r.tg1 = __ldg(&tgt[bt + 37 + lane]);
    r.tg2 = (lane < 16) ? __ldg(&tgt[bt + 69 + lane])  : 0.0f;
    return r;
}

__device__ __forceinline__ float iou_vs(
    float tx1, float ty1, float tx2, float ty2,
    float px, float py, float pw, float ph,
    float fi, float fj)
{
    const float invS = 1.0f / 7.0f;
    float xc = (px + fj) * invS;
    float yc = (py + fi) * invS;
    float x1 = xc - pw * 0.5f, x2 = xc + pw * 0.5f;
    float y1 = yc - ph * 0.5f, y2 = yc + ph * 0.5f;
    float iw = fmaxf(fminf(tx2, x2) - fmaxf(tx1, x1), 0.0f);
    float ih = fmaxf(fminf(ty2, y2) - fmaxf(ty1, y1), 0.0f);
    float inter = iw * ih;
    float area_a = (tx2 - tx1) * (ty2 - ty1);
    float area_b = (x2 - x1) * (y2 - y1);
    return inter / (area_a + area_b - inter + 1e-6f);
}

__global__ void __launch_bounds__(THREADS)
yolo_loss_kernel(const float* __restrict__ pred,
                 const float* __restrict__ tgt,
                 int ncells, float* __restrict__ out, double inv_bs)
{
    __shared__ int   s_list[TILE];
    __shared__ int   s_cnt;
    __shared__ float s_red[5][NWARPS];
    __shared__ bool  s_last;

    const int tid  = threadIdx.x;
    const int lane = tid & 31;
    const int wid  = tid >> 5;

    if (tid == 0) s_cnt = 0;
    __syncthreads();

    const int base = blockIdx.x * TILE;

    float a_cn = 0.0f;

    // ---------------- Phase 1: scan + noobj loss + compact ----------------
    float tc_v[PERT], pc_v[PERT];
    #pragma unroll
    for (int k = 0; k < PERT; k++) {
        int cell = base + k * THREADS + tid;
        tc_v[k] = 0.0f;
        pc_v[k] = 0.0f;
        if (cell < ncells) {
            tc_v[k] = __ldg(&tgt[(long long)cell * TGT_D + 4]);
            pc_v[k] = __ldg(&pred[(long long)cell * PRED_D + 9]);
        }
    }
    #pragma unroll
    for (int k = 0; k < PERT; k++) {
        int cell = base + k * THREADS + tid;
        if (cell < ncells) {
            if (tc_v[k] == 0.0f) {
                a_cn += pc_v[k] * pc_v[k];
            } else {
                int pos = atomicAdd(&s_cnt, 1);
                s_list[pos] = cell;
            }
        }
    }
    __syncthreads();

    const int nobj = s_cnt;

    // ---------------- Phase 2: object cells, 2-deep pipelined -------------
    float a_xy = 0.0f, a_wh = 0.0f, a_co = 0.0f, a_cls = 0.0f;

    int k = wid;
    int curcell = (k < nobj) ? s_list[k] : -1;
    Ld cur;
    if (curcell >= 0) cur = load_cell(pred, tgt, curcell, lane);

    while (curcell >= 0) {
        // Prefetch next cell's data before consuming current
        int kn = k + NWARPS;
        int nextcell = (kn < nobj) ? s_list[kn] : -1;
        Ld nxt;
        if (nextcell >= 0) nxt = load_cell(pred, tgt, nextcell, lane);

        // ---- consume current ----
        {
            float d0 = cur.tg0 - cur.pc0;
            float d1 = cur.tg1 - cur.pc1;
            float d2 = cur.tg2 - cur.pc2;
            a_cls += d0 * d0 + d1 * d1 + d2 * d2;

            float p0 = __shfl_sync(0xffffffffu, cur.pb, 0);
            float p1 = __shfl_sync(0xffffffffu, cur.pb, 1);
            float p2 = __shfl_sync(0xffffffffu, cur.pb, 2);
            float p3 = __shfl_sync(0xffffffffu, cur.pb, 3);
            float p5 = __shfl_sync(0xffffffffu, cur.pb, 5);
            float p6 = __shfl_sync(0xffffffffu, cur.pb, 6);
            float p7 = __shfl_sync(0xffffffffu, cur.pb, 7);
            float p8 = __shfl_sync(0xffffffffu, cur.pb, 8);
            float p9 = __shfl_sync(0xffffffffu, cur.pb, 9);
            float t0 = __shfl_sync(0xffffffffu, cur.tb, 0);
            float t1 = __shfl_sync(0xffffffffu, cur.tb, 1);
            float t2 = __shfl_sync(0xffffffffu, cur.tb, 2);
            float t3 = __shfl_sync(0xffffffffu, cur.tb, 3);
            float t4 = __shfl_sync(0xffffffffu, cur.tb, 4);

            const int ij = curcell % 49;
            const float fi = (float)(ij / 7);
            const float fj = (float)(ij % 7);

            const float invS = 1.0f / 7.0f;
            float txc = (t0 + fj) * invS;
            float tyc = (t1 + fi) * invS;
            float tx1 = txc - t2 * 0.5f, tx2c = txc + t2 * 0.5f;
            float ty1 = tyc - t3 * 0.5f, ty2c = tyc + t3 * 0.5f;

            float iou0 = iou_vs(tx1, ty1, tx2c, ty2c, p0, p1, p2, p3, fi, fj);
            float iou1 = iou_vs(tx1, ty1, tx2c, ty2c, p5, p6, p7, p8, fi, fj);

            bool sel = (iou0 > iou1);
            float sx = sel ? p5 : p0;
            float sy = sel ? p6 : p1;
            float sw = sel ? p7 : p2;
            float sh = sel ? p8 : p3;

            if (lane == 0) {
                float dx = t0 - sx, dy = t1 - sy;
                a_xy += dx * dx + dy * dy;
                float dw = sqrtf(t2) - sqrtf(fmaxf(sw, 0.0f));
                float dh = sqrtf(t3) - sqrtf(fmaxf(sh, 0.0f));
                a_wh += dw * dw + dh * dh;
                float dc = t4 - p9;
                a_co += dc * dc;
            }
        }

        cur = nxt;
        curcell = nextcell;
        k = kn;
    }

    // ---------------- Reduction ----------------
    #pragma unroll
    for (int off = 16; off > 0; off >>= 1) {
        a_xy  += __shfl_xor_sync(0xffffffffu, a_xy,  off);
        a_wh  += __shfl_xor_sync(0xffffffffu, a_wh,  off);
        a_co  += __shfl_xor_sync(0xffffffffu, a_co,  off);
        a_cn  += __shfl_xor_sync(0xffffffffu, a_cn,  off);
        a_cls += __shfl_xor_sync(0xffffffffu, a_cls, off);
    }

    if (lane == 0) {
        s_red[0][wid] = a_xy;
        s_red[1][wid] = a_wh;
        s_red[2][wid] = a_co;
        s_red[3][wid] = a_cn;
        s_red[4][wid] = a_cls;
    }
    __syncthreads();

    if (tid < 5) {
        double sum = 0.0;
        #pragma unroll
        for (int w = 0; w < NWARPS; w++) sum += (double)s_red[tid][w];
        atomicAdd(&g_acc[tid], sum);
    }
    __syncthreads();

    // ---------------- Last block finalizes + resets ----------------
    if (tid == 0) {
        __threadfence();
        unsigned int t = atomicAdd(&g_done, 1u);
        s_last = (t == gridDim.x - 1);
    }
    __syncthreads();

    if (s_last && tid == 0) {
        __threadfence();
        double lxy  = atomicAdd(&g_acc[0], 0.0) * inv_bs;
        double lwh  = atomicAdd(&g_acc[1], 0.0) * inv_bs;
        double lco  = atomicAdd(&g_acc[2], 0.0) * inv_bs;
        double lcn  = atomicAdd(&g_acc[3], 0.0) * inv_bs;
        double lcls = atomicAdd(&g_acc[4], 0.0) * inv_bs;
        double loss = (5.0 * lxy + 5.0 * lwh + lco + 0.5 * lcn + lcls) * inv_bs;
        out[0] = (float)loss;
        out[1] = (float)lxy;
        out[2] = (float)lwh;
        out[3] = (float)lco;
        out[4] = (float)lcn;
        out[5] = (float)lcls;
        // Reset state for next replay (deterministic across graph replays)
        g_acc[0] = 0.0; g_acc[1] = 0.0; g_acc[2] = 0.0;
        g_acc[3] = 0.0; g_acc[4] = 0.0;
        __threadfence();
        g_done = 0u;
    }
}

extern "C" void kernel_launch(void* const* d_in, const int* in_sizes, int n_in,
                              void* d_out, int out_size)
{
    const float* pred = (const float*)d_in[0];
    const float* tgt  = (const float*)d_in[1];
    float* out = (float*)d_out;

    const int N = in_sizes[0] / (49 * PRED_D);
    const int ncells = N * 49;
    const int blocks = (ncells + TILE - 1) / TILE;

    yolo_loss_kernel<<<blocks, THREADS>>>(pred, tgt, ncells, out, 1.0 / (double)N);
}

// round 5
// speedup vs baseline: 1.6648x; 1.4225x over previous
#include <cuda_runtime.h>

#define NCLS 80
#define PRED_D 90   // B*5 + C
#define TGT_D 85    // 5 + C
#define THREADS 256
#define TILE 256
#define NWARPS (THREADS / 32)

// Accumulators: [0]=xy [1]=wh [2]=conf_obj [3]=conf_noobj [4]=class
__device__ double g_acc[5];
__device__ unsigned int g_done;

__device__ __forceinline__ float iou_vs(
    float tx1, float ty1, float tx2, float ty2,
    float px, float py, float pw, float ph,
    float fi, float fj)
{
    const float invS = 1.0f / 7.0f;
    float xc = (px + fj) * invS;
    float yc = (py + fi) * invS;
    float x1 = xc - pw * 0.5f, x2 = xc + pw * 0.5f;
    float y1 = yc - ph * 0.5f, y2 = yc + ph * 0.5f;
    float iw = fmaxf(fminf(tx2, x2) - fmaxf(tx1, x1), 0.0f);
    float ih = fmaxf(fminf(ty2, y2) - fmaxf(ty1, y1), 0.0f);
    float inter = iw * ih;
    float area_a = (tx2 - tx1) * (ty2 - ty1);
    float area_b = (x2 - x1) * (y2 - y1);
    return inter / (area_a + area_b - inter + 1e-6f);
}

__global__ void __launch_bounds__(THREADS)
yolo_loss_kernel(const float* __restrict__ pred,
                 const float* __restrict__ tgt,
                 int ncells, float* __restrict__ out, double inv_bs)
{
    __shared__ int   s_list[TILE];
    __shared__ int   s_cnt;
    __shared__ float s_red[5][NWARPS];
    __shared__ bool  s_last;

    const int tid  = threadIdx.x;
    const int lane = tid & 31;
    const int wid  = tid >> 5;

    if (tid == 0) s_cnt = 0;
    __syncthreads();

    const int cell0 = blockIdx.x * TILE + tid;

    float a_cn = 0.0f;

    // ---------------- Phase 1: scan + noobj loss + ballot compaction ------
    {
        float tc = 0.0f, pc = 0.0f;
        bool valid = (cell0 < ncells);
        if (valid) {
            tc = __ldg(&tgt[(long long)cell0 * TGT_D + 4]);
            pc = __ldg(&pred[(long long)cell0 * PRED_D + 9]);
        }
        bool isobj = valid && (tc != 0.0f);
        if (valid && !isobj) a_cn += pc * pc;

        unsigned int m = __ballot_sync(0xffffffffu, isobj);
        int nwobj = __popc(m);
        int wbase = 0;
        if (lane == 0 && nwobj > 0) wbase = atomicAdd(&s_cnt, nwobj);
        wbase = __shfl_sync(0xffffffffu, wbase, 0);
        if (isobj) {
            int pos = wbase + __popc(m & ((1u << lane) - 1u));
            s_list[pos] = cell0;
        }
    }
    __syncthreads();

    const int nobj = s_cnt;

    float a_xy = 0.0f, a_wh = 0.0f, a_co = 0.0f, a_cls = 0.0f;

    // ---------------- Phase 2a: box losses, thread-per-object-cell --------
    // pred row stride = 360B (8-aligned) -> float2 loads are safe.
    // tgt row stride = 340B (4-aligned) -> scalar loads only.
    for (int k = tid; k < nobj; k += THREADS) {
        const int cell = s_list[k];
        const long long bp = (long long)cell * PRED_D;
        const long long bt = (long long)cell * TGT_D;

        float2 b0 = __ldg((const float2*)(pred + bp));       // p0,p1
        float2 b1 = __ldg((const float2*)(pred + bp + 2));   // p2,p3
        float2 b2 = __ldg((const float2*)(pred + bp + 4));   // p4,p5
        float2 b3 = __ldg((const float2*)(pred + bp + 6));   // p6,p7
        float2 b4 = __ldg((const float2*)(pred + bp + 8));   // p8,p9
        float t0 = __ldg(&tgt[bt + 0]);
        float t1 = __ldg(&tgt[bt + 1]);
        float t2 = __ldg(&tgt[bt + 2]);
        float t3 = __ldg(&tgt[bt + 3]);
        float t4 = __ldg(&tgt[bt + 4]);

        const int ij = cell % 49;
        const float fi = (float)(ij / 7);
        const float fj = (float)(ij % 7);

        const float invS = 1.0f / 7.0f;
        float txc = (t0 + fj) * invS;
        float tyc = (t1 + fi) * invS;
        float tx1 = txc - t2 * 0.5f, tx2c = txc + t2 * 0.5f;
        float ty1 = tyc - t3 * 0.5f, ty2c = tyc + t3 * 0.5f;

        float iou0 = iou_vs(tx1, ty1, tx2c, ty2c, b0.x, b0.y, b1.x, b1.y, fi, fj);
        float iou1 = iou_vs(tx1, ty1, tx2c, ty2c, b2.y, b3.x, b3.y, b4.x, fi, fj);

        bool sel = (iou0 > iou1);   // true -> second box
        float sx = sel ? b2.y : b0.x;
        float sy = sel ? b3.x : b0.y;
        float sw = sel ? b3.y : b1.x;
        float sh = sel ? b4.x : b1.y;

        float dx = t0 - sx, dy = t1 - sy;
        a_xy += dx * dx + dy * dy;

        float dw = sqrtf(t2) - sqrtf(fmaxf(sw, 0.0f));
        float dh = sqrtf(t3) - sqrtf(fmaxf(sh, 0.0f));
        a_wh += dw * dw + dh * dh;

        float dc = t4 - b4.y;
        a_co += dc * dc;
    }

    // ---------------- Phase 2b: class loss, warp-per-cell, pipelined ------
    {
        int k = wid;
        int cell = (k < nobj) ? s_list[k] : -1;
        float pc0 = 0, pc1 = 0, pc2 = 0, tg0 = 0, tg1 = 0, tg2 = 0;
        if (cell >= 0) {
            const long long bp = (long long)cell * PRED_D;
            const long long bt = (long long)cell * TGT_D;
            pc0 = __ldg(&pred[bp + 10 + lane]);
            pc1 = __ldg(&pred[bp + 42 + lane]);
            pc2 = (lane < 16) ? __ldg(&pred[bp + 74 + lane]) : 0.0f;
            tg0 = __ldg(&tgt[bt + 5 + lane]);
            tg1 = __ldg(&tgt[bt + 37 + lane]);
            tg2 = (lane < 16) ? __ldg(&tgt[bt + 69 + lane]) : 0.0f;
        }

        while (cell >= 0) {
            int kn = k + NWARPS;
            int ncell = (kn < nobj) ? s_list[kn] : -1;
            float npc0 = 0, npc1 = 0, npc2 = 0, ntg0 = 0, ntg1 = 0, ntg2 = 0;
            if (ncell >= 0) {
                const long long bp = (long long)ncell * PRED_D;
                const long long bt = (long long)ncell * TGT_D;
                npc0 = __ldg(&pred[bp + 10 + lane]);
                npc1 = __ldg(&pred[bp + 42 + lane]);
                npc2 = (lane < 16) ? __ldg(&pred[bp + 74 + lane]) : 0.0f;
                ntg0 = __ldg(&tgt[bt + 5 + lane]);
                ntg1 = __ldg(&tgt[bt + 37 + lane]);
                ntg2 = (lane < 16) ? __ldg(&tgt[bt + 69 + lane]) : 0.0f;
            }

            float d0 = tg0 - pc0, d1 = tg1 - pc1, d2 = tg2 - pc2;
            a_cls += d0 * d0 + d1 * d1 + d2 * d2;

            pc0 = npc0; pc1 = npc1; pc2 = npc2;
            tg0 = ntg0; tg1 = ntg1; tg2 = ntg2;
            cell = ncell;
            k = kn;
        }
    }

    // ---------------- Reduction ----------------
    #pragma unroll
    for (int off = 16; off > 0; off >>= 1) {
        a_xy  += __shfl_xor_sync(0xffffffffu, a_xy,  off);
        a_wh  += __shfl_xor_sync(0xffffffffu, a_wh,  off);
        a_co  += __shfl_xor_sync(0xffffffffu, a_co,  off);
        a_cn  += __shfl_xor_sync(0xffffffffu, a_cn,  off);
        a_cls += __shfl_xor_sync(0xffffffffu, a_cls, off);
    }

    if (lane == 0) {
        s_red[0][wid] = a_xy;
        s_red[1][wid] = a_wh;
        s_red[2][wid] = a_co;
        s_red[3][wid] = a_cn;
        s_red[4][wid] = a_cls;
    }
    __syncthreads();

    if (tid < 5) {
        double sum = 0.0;
        #pragma unroll
        for (int w = 0; w < NWARPS; w++) sum += (double)s_red[tid][w];
        atomicAdd(&g_acc[tid], sum);
    }
    __syncthreads();

    // ---------------- Last block finalizes + resets ----------------
    if (tid == 0) {
        __threadfence();
        unsigned int t = atomicAdd(&g_done, 1u);
        s_last = (t == gridDim.x - 1);
    }
    __syncthreads();

    if (s_last && tid == 0) {
        __threadfence();
        double lxy  = atomicAdd(&g_acc[0], 0.0) * inv_bs;
        double lwh  = atomicAdd(&g_acc[1], 0.0) * inv_bs;
        double lco  = atomicAdd(&g_acc[2], 0.0) * inv_bs;
        double lcn  = atomicAdd(&g_acc[3], 0.0) * inv_bs;
        double lcls = atomicAdd(&g_acc[4], 0.0) * inv_bs;
        double loss = (5.0 * lxy + 5.0 * lwh + lco + 0.5 * lcn + lcls) * inv_bs;
        out[0] = (float)loss;
        out[1] = (float)lxy;
        out[2] = (float)lwh;
        out[3] = (float)lco;
        out[4] = (float)lcn;
        out[5] = (float)lcls;
        g_acc[0] = 0.0; g_acc[1] = 0.0; g_acc[2] = 0.0;
        g_acc[3] = 0.0; g_acc[4] = 0.0;
        __threadfence();
        g_done = 0u;
    }
}

extern "C" void kernel_launch(void* const* d_in, const int* in_sizes, int n_in,
                              void* d_out, int out_size)
{
    const float* pred = (const float*)d_in[0];
    const float* tgt  = (const float*)d_in[1];
    float* out = (float*)d_out;

    const int N = in_sizes[0] / (49 * PRED_D);
    const int ncells = N * 49;
    const int blocks = (ncells + TILE - 1) / TILE;

    yolo_loss_kernel<<<blocks, THREADS>>>(pred, tgt, ncells, out, 1.0 / (double)N);
}